// round 17
// baseline (speedup 1.0000x reference)
#include <cuda_runtime.h>

#define B 128
#define K 17
#define HW 9216          // 96*96
#define NVEC (HW/4)      // 2304
#define TOPK 8
#define THREADS1 256
#define NPJ (B * K)      // 2176
#define JPB 2            // joints per block
#define NBLK (NPJ / JPB) // 1088

__device__ float g_per_joint[B * K];

__global__ void __launch_bounds__(THREADS1, 4)
mse_per_joint_kernel(const float* __restrict__ pred,
                     const float* __restrict__ gt,
                     const float* __restrict__ tw) {
    const int bk0 = blockIdx.x * JPB;             // first joint of this block
    const int tid = threadIdx.x;
    const float4* __restrict__ p0 = reinterpret_cast<const float4*>(pred + (size_t)bk0 * HW);
    const float4* __restrict__ g0 = reinterpret_cast<const float4*>(gt   + (size_t)bk0 * HW);
    const float4* __restrict__ p1 = p0 + NVEC;
    const float4* __restrict__ g1 = g0 + NVEC;

    float acc0 = 0.0f, acc1 = 0.0f;
    #pragma unroll
    for (int j = 0; j < NVEC / THREADS1; j++) {   // 9 iters, 4 indep loads each
        const int i = tid + j * THREADS1;
        float4 a0 = p0[i];
        float4 b0 = g0[i];
        float4 a1 = p1[i];
        float4 b1 = g1[i];
        float d0 = a0.x - b0.x, d1 = a0.y - b0.y,
              d2 = a0.z - b0.z, d3 = a0.w - b0.w;
        acc0 += d0 * d0 + d1 * d1 + d2 * d2 + d3 * d3;
        d0 = a1.x - b1.x; d1 = a1.y - b1.y;
        d2 = a1.z - b1.z; d3 = a1.w - b1.w;
        acc1 += d0 * d0 + d1 * d1 + d2 * d2 + d3 * d3;
    }

    // warp reduce both accumulators
    #pragma unroll
    for (int off = 16; off > 0; off >>= 1) {
        acc0 += __shfl_down_sync(0xFFFFFFFFu, acc0, off);
        acc1 += __shfl_down_sync(0xFFFFFFFFu, acc1, off);
    }

    __shared__ float warp_sums[JPB][THREADS1 / 32];
    const int lane = tid & 31;
    const int wid  = tid >> 5;
    if (lane == 0) {
        warp_sums[0][wid] = acc0;
        warp_sums[1][wid] = acc1;
    }
    __syncthreads();

    // warp 0 folds joint 0, warp 1 folds joint 1
    if (wid < JPB) {
        float v = (lane < THREADS1 / 32) ? warp_sums[wid][lane] : 0.0f;
        #pragma unroll
        for (int off = 4; off > 0; off >>= 1)
            v += __shfl_down_sync(0xFFFFFFFFu, v, off);
        if (lane == 0) {
            const int bk = bk0 + wid;
            const float w = tw[bk];
            g_per_joint[bk] = v * w * w * (1.0f / (float)HW);
        }
    }
}

// Single-warp, barrier-free, smem-free top-k + mean.
__global__ void __launch_bounds__(32, 1)
ohkm_topk_kernel(float* __restrict__ out) {
    const int lane = threadIdx.x;

    float total = 0.0f;
    #pragma unroll
    for (int q = 0; q < B / 32; q++) {            // 4 samples per lane
        const int b = lane + q * 32;
        const float* __restrict__ row = &g_per_joint[b * K];

        // issue all 17 loads independently (one overlapped L2 round trip)
        float x[K];
        #pragma unroll
        for (int i = 0; i < K; i++) x[i] = __ldg(&row[i]);

        // register insertion network: sorted top-8, static indices only
        float t[TOPK];
        #pragma unroll
        for (int j = 0; j < TOPK; j++) t[j] = -3.4e38f;
        #pragma unroll
        for (int i = 0; i < K; i++) {
            float v = x[i];
            #pragma unroll
            for (int j = 0; j < TOPK; j++) {
                float o = t[j];
                bool gtp = v > o;
                t[j] = gtp ? v : o;
                v    = gtp ? o : v;
            }
        }
        #pragma unroll
        for (int j = 0; j < TOPK; j++) total += t[j];
    }

    // warp shuffle reduce, then one store — no barriers anywhere
    #pragma unroll
    for (int off = 16; off > 0; off >>= 1)
        total += __shfl_down_sync(0xFFFFFFFFu, total, off);

    if (lane == 0)
        out[0] = total * (1.0f / (float)(B * TOPK));
}

extern "C" void kernel_launch(void* const* d_in, const int* in_sizes, int n_in,
                              void* d_out, int out_size) {
    const float* pred = (const float*)d_in[0];   // output [B,K,H,W]
    const float* gt   = (const float*)d_in[1];   // target [B,K,H,W]
    const float* tw   = (const float*)d_in[2];   // target_weight [B,K,1]
    float* out = (float*)d_out;

    mse_per_joint_kernel<<<NBLK, THREADS1>>>(pred, gt, tw);
    ohkm_topk_kernel<<<1, 32>>>(out);
}